// round 9
// baseline (speedup 1.0000x reference)
#include <cuda_runtime.h>
#include <cuda_bf16.h>
#include <cstdint>

#define B_    64
#define T_    512
#define F_    1024
#define H_    52
#define START_ 50
#define STOP_  51

__device__ float g_emitT[(size_t)B_ * H_ * T_]; // emit transposed [b][h][t]
__device__ float g_diff[B_];

// ---------- packed fp32x2 helpers ----------
__device__ __forceinline__ unsigned long long pk2(float lo, float hi) {
    unsigned long long d;
    asm("mov.b64 %0, {%1, %2};" : "=l"(d) : "r"(__float_as_uint(lo)), "r"(__float_as_uint(hi)));
    return d;
}
__device__ __forceinline__ void upk2(unsigned long long v, float& lo, float& hi) {
    unsigned int a, b;
    asm("mov.b64 {%0, %1}, %2;" : "=r"(a), "=r"(b) : "l"(v));
    lo = __uint_as_float(a); hi = __uint_as_float(b);
}
__device__ __forceinline__ unsigned long long fma2(unsigned long long a, unsigned long long b,
                                                   unsigned long long c) {
    unsigned long long d;
    asm("fma.rn.f32x2 %0, %1, %2, %3;" : "=l"(d) : "l"(a), "l"(b), "l"(c));
    return d;
}
__device__ __forceinline__ unsigned long long add2(unsigned long long a, unsigned long long b) {
    unsigned long long d;
    asm("add.rn.f32x2 %0, %1, %2;" : "=l"(d) : "l"(a), "l"(b));
    return d;
}

// ============================================================
// Kernel 1: emit GEMM — FROZEN best-measured config (91.4us).
// 128 blocks x 256 threads, 256-row tile, 4 rows x 7 pairs/thread.
// Output transposed: g_emitT[b][h][t].
// ============================================================
__global__ void __launch_bounds__(256, 1)
emit_gemm_kernel(const float* __restrict__ feat, const float* __restrict__ W,
                 const float* __restrict__ bias) {
    __shared__ float sF[32 * 257];
    __shared__ float sW[32 * 58];

    const int tid = threadIdx.x;
    const int cg = tid >> 6;
    const int rt = tid & 63;
    const int blockRow = blockIdx.x * 256;

    const int lrow = tid >> 3;
    const int ljj  = tid & 7;
    const int wkk  = tid & 31;
    const int whb  = tid >> 5;

    unsigned long long acc[4][7];
#pragma unroll
    for (int r = 0; r < 4; r++)
#pragma unroll
        for (int j = 0; j < 7; j++) acc[r][j] = 0ULL;

    float4 fv[8];
    float  wv[7];

    auto load_chunk = [&](int k0) {
#pragma unroll
        for (int it = 0; it < 8; it++) {
            int row = lrow + it * 32;
            fv[it] = *reinterpret_cast<const float4*>(
                &feat[(size_t)(blockRow + row) * F_ + k0 + ljj * 4]);
        }
#pragma unroll
        for (int it = 0; it < 7; it++) {
            int hh = whb + it * 8;
            wv[it] = (hh < H_) ? W[(size_t)hh * F_ + k0 + wkk] : 0.0f;
        }
    };
    auto store_chunk = [&]() {
#pragma unroll
        for (int it = 0; it < 8; it++) {
            int row = lrow + it * 32;
            sF[(ljj * 4 + 0) * 257 + row] = fv[it].x;
            sF[(ljj * 4 + 1) * 257 + row] = fv[it].y;
            sF[(ljj * 4 + 2) * 257 + row] = fv[it].z;
            sF[(ljj * 4 + 3) * 257 + row] = fv[it].w;
        }
#pragma unroll
        for (int it = 0; it < 7; it++) sW[wkk * 58 + whb + it * 8] = wv[it];
    };

    load_chunk(0);
    for (int k0 = 0; k0 < F_; k0 += 32) {
        __syncthreads();
        store_chunk();
        __syncthreads();
        if (k0 + 32 < F_) load_chunk(k0 + 32);

#pragma unroll 4
        for (int kk = 0; kk < 32; kk++) {
            float f0 = sF[kk * 257 + rt];
            float f1 = sF[kk * 257 + rt + 64];
            float f2 = sF[kk * 257 + rt + 128];
            float f3 = sF[kk * 257 + rt + 192];
            unsigned long long p0 = pk2(f0, f0);
            unsigned long long p1 = pk2(f1, f1);
            unsigned long long p2 = pk2(f2, f2);
            unsigned long long p3 = pk2(f3, f3);
#pragma unroll
            for (int j = 0; j < 7; j++) {
                unsigned long long w2 = *reinterpret_cast<const unsigned long long*>(
                    &sW[kk * 58 + cg * 14 + 2 * j]);
                acc[0][j] = fma2(p0, w2, acc[0][j]);
                acc[1][j] = fma2(p1, w2, acc[1][j]);
                acc[2][j] = fma2(p2, w2, acc[2][j]);
                acc[3][j] = fma2(p3, w2, acc[3][j]);
            }
        }
    }

#pragma unroll
    for (int r = 0; r < 4; r++) {
        int row = blockRow + rt + r * 64;
        int b = row >> 9;
        int t = row & 511;
        size_t bbase = (size_t)b * (H_ * T_);
#pragma unroll
        for (int j = 0; j < 7; j++) {
            int col = cg * 14 + 2 * j;
            if (col + 1 < H_) {
                float lo, hi;
                upk2(acc[r][j], lo, hi);
                lo += __ldg(&bias[col]);
                hi += __ldg(&bias[col + 1]);
                g_emitT[bbase + (size_t)col * T_ + t] = lo;
                g_emitT[bbase + (size_t)(col + 1) * T_ + t] = hi;
            }
        }
    }
}

// ============================================================
// Kernel 2: CRF forward — ONE warp per batch, 26 active lanes,
// lane dp owns dest states (2dp, 2dp+1). p kept in smem PRE-SPLATTED
// as (p,p) pairs => each LDS.128 yields 2 fma2 operands (no movs).
// Double-buffered p, exactly ONE __syncwarp per step, no block
// barrier, renorm scalar via shfl from lane 0 every 4 steps.
// ============================================================
__global__ void __launch_bounds__(32, 1)
crf_scan_kernel(const float* __restrict__ transition, const float* __restrict__ masks,
                const int* __restrict__ tags) {
    const int b = blockIdx.x;
    const int lane = threadIdx.x;
    const bool act = (lane < 26);
    const int dp = act ? lane : 0;
    const int d0 = 2 * dp, d1 = 2 * dp + 1;
    const int base = b * T_;
    const unsigned FULL = 0xFFFFFFFFu;

    __shared__ __align__(16) float p2s[2][104];   // [buf][52 splat pairs]

    const float* embB = &g_emitT[(size_t)b * (H_ * T_)];

    // ---- gold score (all 32 lanes) ----
    float gold = 0.0f, msum = 0.0f;
    for (int t = lane; t < T_; t += 32) {
        float mk = masks[base + t];
        int tg = tags[base + t];
        int pv = (t == 0) ? START_ : tags[base + t - 1];
        gold += mk * (embB[(size_t)tg * T_ + t] + transition[tg * H_ + pv]);
        msum += mk;
    }
#pragma unroll
    for (int s = 16; s > 0; s >>= 1) {
        gold += __shfl_xor_sync(FULL, gold, s);
        msum += __shfl_xor_sync(FULL, msum, s);
    }
    int last_pos = (int)(msum + 0.5f);
    int last_tag = (last_pos > 0) ? tags[base + last_pos - 1] : START_;
    gold += transition[STOP_ * H_ + last_tag];

    // ---- E2[src] = (exp(trans[d0][src]), exp(trans[d1][src])) ----
    unsigned long long E2[52];
    {
        const float* r0 = &transition[d0 * H_];
        const float* r1 = &transition[d1 * H_];
#pragma unroll
        for (int s = 0; s < H_; s++) E2[s] = pk2(__expf(r0[s]), __expf(r1[s]));
    }

    // ---- init: p = onehot(START) ----
    float po0 = (d0 == START_) ? 1.0f : 0.0f;   // dp==25 -> d0==50==START
    float po1 = 0.0f;                            // d1 is never START
    if (act) {
        float4 sp = make_float4(po0, po0, po1, po1);
        *reinterpret_cast<float4*>(&p2s[0][4 * dp]) = sp;
    }
    float offset = 0.0f;

    // ---- emit/mask pipeline (4-step blocks, ~8-12 step lookahead) ----
    const float* e0 = embB + (size_t)d0 * T_;
    const float* e1 = embB + (size_t)d1 * T_;
    const float4* m4 = reinterpret_cast<const float4*>(&masks[base]);

    float eC0[4], eC1[4];
    float4 rn0, rn1, rrn0, rrn1, mkC, mkN, mkN2;
    {
        float4 a = *reinterpret_cast<const float4*>(e0);
        float4 c = *reinterpret_cast<const float4*>(e1);
        eC0[0] = __expf(a.x); eC0[1] = __expf(a.y); eC0[2] = __expf(a.z); eC0[3] = __expf(a.w);
        eC1[0] = __expf(c.x); eC1[1] = __expf(c.y); eC1[2] = __expf(c.z); eC1[3] = __expf(c.w);
        rn0  = *reinterpret_cast<const float4*>(e0 + 4);
        rn1  = *reinterpret_cast<const float4*>(e1 + 4);
        rrn0 = *reinterpret_cast<const float4*>(e0 + 8);
        rrn1 = *reinterpret_cast<const float4*>(e1 + 8);
        mkC = m4[0]; mkN = m4[1]; mkN2 = m4[2];
    }
    __syncwarp();

    int cur = 0;
    const int NB = T_ / 4;  // 128
    for (int tb = 0; tb < NB; tb++) {
        float4 l0, l1, lm;
        const bool hv = (tb + 3 < NB);
        if (hv) {
            l0 = *reinterpret_cast<const float4*>(e0 + (tb + 3) * 4);
            l1 = *reinterpret_cast<const float4*>(e1 + (tb + 3) * 4);
            lm = m4[tb + 3];
        }
        float eN0[4], eN1[4];
        eN0[0] = __expf(rn0.x); eN0[1] = __expf(rn0.y); eN0[2] = __expf(rn0.z); eN0[3] = __expf(rn0.w);
        eN1[0] = __expf(rn1.x); eN1[1] = __expf(rn1.y); eN1[2] = __expf(rn1.z); eN1[3] = __expf(rn1.w);

        float rinv = 1.0f;
        if (tb) {
            float r = __shfl_sync(FULL, po0, 0);  // p[state 0] lives in lane 0
            rinv = 1.0f / r;
            offset += __logf(r);
        }
        float mk[4] = {mkC.x, mkC.y, mkC.z, mkC.w};

#pragma unroll
        for (int s = 0; s < 4; s++) {
            const ulonglong2* u = reinterpret_cast<const ulonglong2*>(&p2s[cur][0]);
            unsigned long long A0 = 0ULL, A1 = 0ULL, A2 = 0ULL, A3 = 0ULL;
#pragma unroll
            for (int q = 0; q < 26; q++) {
                ulonglong2 uq = u[q];
                if (q & 1) { A2 = fma2(E2[2 * q], uq.x, A2); A3 = fma2(E2[2 * q + 1], uq.y, A3); }
                else       { A0 = fma2(E2[2 * q], uq.x, A0); A1 = fma2(E2[2 * q + 1], uq.y, A1); }
            }
            unsigned long long S2 = add2(add2(A0, A1), add2(A2, A3));
            float S0, S1;
            upk2(S2, S0, S1);
            bool on = (mk[s] > 0.5f);
            float n0 = on ? S0 * eC0[s] : po0;
            float n1 = on ? S1 * eC1[s] : po1;
            if (s == 0) { n0 *= rinv; n1 *= rinv; }
            if (act) {
                float4 sp = make_float4(n0, n0, n1, n1);
                *reinterpret_cast<float4*>(&p2s[cur ^ 1][4 * dp]) = sp;
            }
            po0 = n0; po1 = n1;
            cur ^= 1;
            __syncwarp();
        }

        eC0[0] = eN0[0]; eC0[1] = eN0[1]; eC0[2] = eN0[2]; eC0[3] = eN0[3];
        eC1[0] = eN1[0]; eC1[1] = eN1[1]; eC1[2] = eN1[2]; eC1[3] = eN1[3];
        rn0 = rrn0; rn1 = rrn1;
        mkC = mkN; mkN = mkN2;
        if (hv) { rrn0 = l0; rrn1 = l1; mkN2 = lm; }
    }

    // ---- final: fwd = offset + log(sum_h p[h] * exp(trans[STOP,h])) ----
    float term = 0.0f;
    if (act) {
        term = po0 * __expf(transition[STOP_ * H_ + d0])
             + po1 * __expf(transition[STOP_ * H_ + d1]);
    }
#pragma unroll
    for (int s = 16; s > 0; s >>= 1) term += __shfl_xor_sync(FULL, term, s);
    if (lane == 0) {
        g_diff[b] = offset + __logf(term) - gold;
    }
}

// ============================================================
// Kernel 3: mean over batches
// ============================================================
__global__ void __launch_bounds__(64)
finalize_kernel(float* __restrict__ out) {
    __shared__ float red[64];
    int tid = threadIdx.x;
    red[tid] = g_diff[tid];
    __syncthreads();
    for (int s = 32; s > 0; s >>= 1) { if (tid < s) red[tid] += red[tid + s]; __syncthreads(); }
    if (tid == 0) out[0] = red[0] * (1.0f / (float)B_);
}

// ============================================================
// launch
// ============================================================
extern "C" void kernel_launch(void* const* d_in, const int* in_sizes, int n_in,
                              void* d_out, int out_size) {
    const float* feat  = (const float*)d_in[0];
    const float* W     = (const float*)d_in[1];
    const float* bias  = (const float*)d_in[2];
    const float* trans = (const float*)d_in[3];
    const float* masks = (const float*)d_in[4];
    const int*   tags  = (const int*)d_in[5];
    float* out = (float*)d_out;

    emit_gemm_kernel<<<128, 256>>>(feat, W, bias);
    crf_scan_kernel<<<B_, 32>>>(trans, masks, tags);
    finalize_kernel<<<1, 64>>>(out);
}

// round 10
// speedup vs baseline: 1.3365x; 1.3365x over previous
#include <cuda_runtime.h>
#include <cuda_bf16.h>
#include <cstdint>

#define B_    64
#define T_    512
#define F_    1024
#define H_    52
#define START_ 50
#define STOP_  51

__device__ float g_emitT[(size_t)B_ * H_ * T_]; // emit transposed [b][h][t]
__device__ float g_diff[B_];

// ---------- packed fp32x2 helpers ----------
__device__ __forceinline__ unsigned long long pk2(float lo, float hi) {
    unsigned long long d;
    asm("mov.b64 %0, {%1, %2};" : "=l"(d) : "r"(__float_as_uint(lo)), "r"(__float_as_uint(hi)));
    return d;
}
__device__ __forceinline__ void upk2(unsigned long long v, float& lo, float& hi) {
    unsigned int a, b;
    asm("mov.b64 {%0, %1}, %2;" : "=r"(a), "=r"(b) : "l"(v));
    lo = __uint_as_float(a); hi = __uint_as_float(b);
}
__device__ __forceinline__ unsigned long long fma2(unsigned long long a, unsigned long long b,
                                                   unsigned long long c) {
    unsigned long long d;
    asm("fma.rn.f32x2 %0, %1, %2, %3;" : "=l"(d) : "l"(a), "l"(b), "l"(c));
    return d;
}
__device__ __forceinline__ unsigned long long add2(unsigned long long a, unsigned long long b) {
    unsigned long long d;
    asm("add.rn.f32x2 %0, %1, %2;" : "=l"(d) : "l"(a), "l"(b));
    return d;
}

// ============================================================
// Kernel 1: emit GEMM — FROZEN best-measured config (~92us).
// ============================================================
__global__ void __launch_bounds__(256, 1)
emit_gemm_kernel(const float* __restrict__ feat, const float* __restrict__ W,
                 const float* __restrict__ bias) {
    __shared__ float sF[32 * 257];
    __shared__ float sW[32 * 58];

    const int tid = threadIdx.x;
    const int cg = tid >> 6;
    const int rt = tid & 63;
    const int blockRow = blockIdx.x * 256;

    const int lrow = tid >> 3;
    const int ljj  = tid & 7;
    const int wkk  = tid & 31;
    const int whb  = tid >> 5;

    unsigned long long acc[4][7];
#pragma unroll
    for (int r = 0; r < 4; r++)
#pragma unroll
        for (int j = 0; j < 7; j++) acc[r][j] = 0ULL;

    float4 fv[8];
    float  wv[7];

    auto load_chunk = [&](int k0) {
#pragma unroll
        for (int it = 0; it < 8; it++) {
            int row = lrow + it * 32;
            fv[it] = *reinterpret_cast<const float4*>(
                &feat[(size_t)(blockRow + row) * F_ + k0 + ljj * 4]);
        }
#pragma unroll
        for (int it = 0; it < 7; it++) {
            int hh = whb + it * 8;
            wv[it] = (hh < H_) ? W[(size_t)hh * F_ + k0 + wkk] : 0.0f;
        }
    };
    auto store_chunk = [&]() {
#pragma unroll
        for (int it = 0; it < 8; it++) {
            int row = lrow + it * 32;
            sF[(ljj * 4 + 0) * 257 + row] = fv[it].x;
            sF[(ljj * 4 + 1) * 257 + row] = fv[it].y;
            sF[(ljj * 4 + 2) * 257 + row] = fv[it].z;
            sF[(ljj * 4 + 3) * 257 + row] = fv[it].w;
        }
#pragma unroll
        for (int it = 0; it < 7; it++) sW[wkk * 58 + whb + it * 8] = wv[it];
    };

    load_chunk(0);
    for (int k0 = 0; k0 < F_; k0 += 32) {
        __syncthreads();
        store_chunk();
        __syncthreads();
        if (k0 + 32 < F_) load_chunk(k0 + 32);

#pragma unroll 4
        for (int kk = 0; kk < 32; kk++) {
            float f0 = sF[kk * 257 + rt];
            float f1 = sF[kk * 257 + rt + 64];
            float f2 = sF[kk * 257 + rt + 128];
            float f3 = sF[kk * 257 + rt + 192];
            unsigned long long p0 = pk2(f0, f0);
            unsigned long long p1 = pk2(f1, f1);
            unsigned long long p2 = pk2(f2, f2);
            unsigned long long p3 = pk2(f3, f3);
#pragma unroll
            for (int j = 0; j < 7; j++) {
                unsigned long long w2 = *reinterpret_cast<const unsigned long long*>(
                    &sW[kk * 58 + cg * 14 + 2 * j]);
                acc[0][j] = fma2(p0, w2, acc[0][j]);
                acc[1][j] = fma2(p1, w2, acc[1][j]);
                acc[2][j] = fma2(p2, w2, acc[2][j]);
                acc[3][j] = fma2(p3, w2, acc[3][j]);
            }
        }
    }

#pragma unroll
    for (int r = 0; r < 4; r++) {
        int row = blockRow + rt + r * 64;
        int b = row >> 9;
        int t = row & 511;
        size_t bbase = (size_t)b * (H_ * T_);
#pragma unroll
        for (int j = 0; j < 7; j++) {
            int col = cg * 14 + 2 * j;
            if (col + 1 < H_) {
                float lo, hi;
                upk2(acc[r][j], lo, hi);
                lo += __ldg(&bias[col]);
                hi += __ldg(&bias[col + 1]);
                g_emitT[bbase + (size_t)col * T_ + t] = lo;
                g_emitT[bbase + (size_t)(col + 1) * T_ + t] = hi;
            }
        }
    }
}

// ============================================================
// Kernel 2: CRF forward via BIDIRECTIONAL scan, 2 warps per batch.
// Warp 0: forward t=0..255  (p_{t+1} = A_t p_t, A_t[d,s]=e_t[d]M[d,s]).
// Warp 1: backward t=511..256 (r_t = A_t^T r_{t+1}, r_512 = exp(trans[STOP,:])).
// fwd = offA + offB + log(sum_h p_256[h] * r_256[h]).  Exact.
// Each warp: 26 active lanes, lane owns states (2dp, 2dp+1); p/r
// pre-splatted in smem as (v,v) pairs; 1 __syncwarp per step.
// Renorm by component 0 every 4 steps (per direction).
// ============================================================
__global__ void __launch_bounds__(64, 1)
crf_scan_kernel(const float* __restrict__ transition, const float* __restrict__ masks,
                const int* __restrict__ tags) {
    const int b = blockIdx.x;
    const int tid = threadIdx.x;
    const int w = tid >> 5;
    const int lane = tid & 31;
    const bool act = (lane < 26);
    const int dp = act ? lane : 0;
    const int d0 = 2 * dp, d1 = 2 * dp + 1;
    const int base = b * T_;
    const unsigned FULL = 0xFFFFFFFFu;

    __shared__ __align__(16) float bufs[2][2][104];  // [warp][parity][52 splat pairs]
    __shared__ float fx[52], bx[52];
    __shared__ float offsm[2], goldsm[2], msumsm[2];

    const float* embB = &g_emitT[(size_t)b * (H_ * T_)];

    // ---- gold partials (both warps, stride 64) ----
    float gold = 0.0f, msum = 0.0f;
    for (int t = tid; t < T_; t += 64) {
        float mk = masks[base + t];
        int tg = tags[base + t];
        int pv = (t == 0) ? START_ : tags[base + t - 1];
        gold += mk * (embB[(size_t)tg * T_ + t] + transition[tg * H_ + pv]);
        msum += mk;
    }
#pragma unroll
    for (int s = 16; s > 0; s >>= 1) {
        gold += __shfl_xor_sync(FULL, gold, s);
        msum += __shfl_xor_sync(FULL, msum, s);
    }
    if (lane == 0) { goldsm[w] = gold; msumsm[w] = msum; }

    const float* e0 = embB + (size_t)d0 * T_;
    const float* e1 = embB + (size_t)d1 * T_;
    const float4* m4 = reinterpret_cast<const float4*>(&masks[base]);
    float (*myb)[104] = bufs[w];

    if (w == 0) {
        // ================= FORWARD: t = 0..255 =================
        unsigned long long E2[52];
        {
            const float* r0 = &transition[d0 * H_];
            const float* r1 = &transition[d1 * H_];
#pragma unroll
            for (int s = 0; s < H_; s++) E2[s] = pk2(__expf(r0[s]), __expf(r1[s]));
        }
        float po0 = (d0 == START_) ? 1.0f : 0.0f;
        float po1 = 0.0f;
        if (act) *reinterpret_cast<float4*>(&myb[0][4 * dp]) = make_float4(po0, po0, po1, po1);
        float offset = 0.0f;

        float eC0[4], eC1[4];
        float4 rn0, rn1, rrn0, rrn1, mkC, mkN, mkN2;
        {
            float4 a = *reinterpret_cast<const float4*>(e0);
            float4 c = *reinterpret_cast<const float4*>(e1);
            eC0[0] = __expf(a.x); eC0[1] = __expf(a.y); eC0[2] = __expf(a.z); eC0[3] = __expf(a.w);
            eC1[0] = __expf(c.x); eC1[1] = __expf(c.y); eC1[2] = __expf(c.z); eC1[3] = __expf(c.w);
            rn0  = *reinterpret_cast<const float4*>(e0 + 4);
            rn1  = *reinterpret_cast<const float4*>(e1 + 4);
            rrn0 = *reinterpret_cast<const float4*>(e0 + 8);
            rrn1 = *reinterpret_cast<const float4*>(e1 + 8);
            mkC = m4[0]; mkN = m4[1]; mkN2 = m4[2];
        }
        __syncwarp();

        int cur = 0;
        for (int tb = 0; tb < 64; tb++) {
            float4 l0, l1, lm;
            const bool hv = (tb + 3 < 64);
            if (hv) {
                l0 = *reinterpret_cast<const float4*>(e0 + (tb + 3) * 4);
                l1 = *reinterpret_cast<const float4*>(e1 + (tb + 3) * 4);
                lm = m4[tb + 3];
            }
            float eN0[4], eN1[4];
            eN0[0] = __expf(rn0.x); eN0[1] = __expf(rn0.y); eN0[2] = __expf(rn0.z); eN0[3] = __expf(rn0.w);
            eN1[0] = __expf(rn1.x); eN1[1] = __expf(rn1.y); eN1[2] = __expf(rn1.z); eN1[3] = __expf(rn1.w);

            float rinv = 1.0f;
            if (tb) {
                float r = __shfl_sync(FULL, po0, 0);
                rinv = 1.0f / r;
                offset += __logf(r);
            }
            float mk[4] = {mkC.x, mkC.y, mkC.z, mkC.w};

#pragma unroll
            for (int s = 0; s < 4; s++) {
                const ulonglong2* u = reinterpret_cast<const ulonglong2*>(&myb[cur][0]);
                unsigned long long A0 = 0ULL, A1 = 0ULL, A2 = 0ULL, A3 = 0ULL;
#pragma unroll
                for (int q = 0; q < 26; q++) {
                    ulonglong2 uq = u[q];
                    if (q & 1) { A2 = fma2(E2[2 * q], uq.x, A2); A3 = fma2(E2[2 * q + 1], uq.y, A3); }
                    else       { A0 = fma2(E2[2 * q], uq.x, A0); A1 = fma2(E2[2 * q + 1], uq.y, A1); }
                }
                unsigned long long S2 = add2(add2(A0, A1), add2(A2, A3));
                float S0, S1;
                upk2(S2, S0, S1);
                bool on = (mk[s] > 0.5f);
                float n0 = on ? S0 * eC0[s] : po0;
                float n1 = on ? S1 * eC1[s] : po1;
                if (s == 0) { n0 *= rinv; n1 *= rinv; }
                if (act) *reinterpret_cast<float4*>(&myb[cur ^ 1][4 * dp]) = make_float4(n0, n0, n1, n1);
                po0 = n0; po1 = n1;
                cur ^= 1;
                __syncwarp();
            }

            eC0[0] = eN0[0]; eC0[1] = eN0[1]; eC0[2] = eN0[2]; eC0[3] = eN0[3];
            eC1[0] = eN1[0]; eC1[1] = eN1[1]; eC1[2] = eN1[2]; eC1[3] = eN1[3];
            rn0 = rrn0; rn1 = rrn1;
            mkC = mkN; mkN = mkN2;
            if (hv) { rrn0 = l0; rrn1 = l1; mkN2 = lm; }
        }
        if (act) { fx[d0] = po0; fx[d1] = po1; }
        if (lane == 0) offsm[0] = offset;
    } else {
        // ================= BACKWARD: t = 511..256 =================
        // Eb2[dd] = (exp(trans[dd][d0]), exp(trans[dd][d1]))  (transposed table)
        unsigned long long E2[52];
        {
#pragma unroll
            for (int dd = 0; dd < H_; dd++)
                E2[dd] = pk2(__expf(transition[dd * H_ + d0]), __expf(transition[dd * H_ + d1]));
        }
        float ro0 = __expf(transition[STOP_ * H_ + d0]);   // r_512
        float ro1 = __expf(transition[STOP_ * H_ + d1]);
        float offset = 0.0f;

        float eC0[4], eC1[4];
        float4 rn0, rn1, rrn0, rrn1, mkC, mkN, mkN2;
        {
            float4 a = *reinterpret_cast<const float4*>(e0 + 127 * 4);
            float4 c = *reinterpret_cast<const float4*>(e1 + 127 * 4);
            eC0[0] = __expf(a.x); eC0[1] = __expf(a.y); eC0[2] = __expf(a.z); eC0[3] = __expf(a.w);
            eC1[0] = __expf(c.x); eC1[1] = __expf(c.y); eC1[2] = __expf(c.z); eC1[3] = __expf(c.w);
            rn0  = *reinterpret_cast<const float4*>(e0 + 126 * 4);
            rn1  = *reinterpret_cast<const float4*>(e1 + 126 * 4);
            rrn0 = *reinterpret_cast<const float4*>(e0 + 125 * 4);
            rrn1 = *reinterpret_cast<const float4*>(e1 + 125 * 4);
            mkC = m4[127]; mkN = m4[126]; mkN2 = m4[125];
        }
        __syncwarp();

        int cur = 0;
        for (int tb = 127; tb >= 64; tb--) {
            float4 l0, l1, lm;
            const bool hv = (tb - 3 >= 64);
            if (hv) {
                l0 = *reinterpret_cast<const float4*>(e0 + (tb - 3) * 4);
                l1 = *reinterpret_cast<const float4*>(e1 + (tb - 3) * 4);
                lm = m4[tb - 3];
            }
            float eN0[4], eN1[4];
            eN0[0] = __expf(rn0.x); eN0[1] = __expf(rn0.y); eN0[2] = __expf(rn0.z); eN0[3] = __expf(rn0.w);
            eN1[0] = __expf(rn1.x); eN1[1] = __expf(rn1.y); eN1[2] = __expf(rn1.z); eN1[3] = __expf(rn1.w);

            float rinv = 1.0f;
            if (tb != 127) {
                float r = __shfl_sync(FULL, ro0, 0);
                rinv = 1.0f / r;
                offset += __logf(r);
            }
            float mk[4] = {mkC.x, mkC.y, mkC.z, mkC.w};

#pragma unroll
            for (int si = 0; si < 4; si++) {
                const int s = 3 - si;   // process t descending within block
                // w = e_t * r, splat to smem
                float w0 = eC0[s] * ro0;
                float w1 = eC1[s] * ro1;
                if (act) *reinterpret_cast<float4*>(&myb[cur][4 * dp]) = make_float4(w0, w0, w1, w1);
                __syncwarp();
                const ulonglong2* u = reinterpret_cast<const ulonglong2*>(&myb[cur][0]);
                unsigned long long A0 = 0ULL, A1 = 0ULL, A2 = 0ULL, A3 = 0ULL;
#pragma unroll
                for (int q = 0; q < 26; q++) {
                    ulonglong2 uq = u[q];
                    if (q & 1) { A2 = fma2(E2[2 * q], uq.x, A2); A3 = fma2(E2[2 * q + 1], uq.y, A3); }
                    else       { A0 = fma2(E2[2 * q], uq.x, A0); A1 = fma2(E2[2 * q + 1], uq.y, A1); }
                }
                unsigned long long S2 = add2(add2(A0, A1), add2(A2, A3));
                float S0, S1;
                upk2(S2, S0, S1);
                bool on = (mk[s] > 0.5f);
                float n0 = on ? S0 : ro0;
                float n1 = on ? S1 : ro1;
                if (s == 3) { n0 *= rinv; n1 *= rinv; }
                ro0 = n0; ro1 = n1;
                cur ^= 1;
            }

            eC0[0] = eN0[0]; eC0[1] = eN0[1]; eC0[2] = eN0[2]; eC0[3] = eN0[3];
            eC1[0] = eN1[0]; eC1[1] = eN1[1]; eC1[2] = eN1[2]; eC1[3] = eN1[3];
            rn0 = rrn0; rn1 = rrn1;
            mkC = mkN; mkN = mkN2;
            if (hv) { rrn0 = l0; rrn1 = l1; mkN2 = lm; }
        }
        if (act) { bx[d0] = ro0; bx[d1] = ro1; }
        if (lane == 0) offsm[1] = offset;
    }

    __syncthreads();
    if (w == 0) {
        float term = act ? (fx[d0] * bx[d0] + fx[d1] * bx[d1]) : 0.0f;
#pragma unroll
        for (int s = 16; s > 0; s >>= 1) term += __shfl_xor_sync(FULL, term, s);
        if (lane == 0) {
            float goldT = goldsm[0] + goldsm[1];
            float msumT = msumsm[0] + msumsm[1];
            int lp = (int)(msumT + 0.5f);
            int lt = (lp > 0) ? tags[base + lp - 1] : START_;
            goldT += transition[STOP_ * H_ + lt];
            g_diff[b] = offsm[0] + offsm[1] + __logf(term) - goldT;
        }
    }
}

// ============================================================
// Kernel 3: mean over batches
// ============================================================
__global__ void __launch_bounds__(64)
finalize_kernel(float* __restrict__ out) {
    __shared__ float red[64];
    int tid = threadIdx.x;
    red[tid] = g_diff[tid];
    __syncthreads();
    for (int s = 32; s > 0; s >>= 1) { if (tid < s) red[tid] += red[tid + s]; __syncthreads(); }
    if (tid == 0) out[0] = red[0] * (1.0f / (float)B_);
}

// ============================================================
// launch
// ============================================================
extern "C" void kernel_launch(void* const* d_in, const int* in_sizes, int n_in,
                              void* d_out, int out_size) {
    const float* feat  = (const float*)d_in[0];
    const float* W     = (const float*)d_in[1];
    const float* bias  = (const float*)d_in[2];
    const float* trans = (const float*)d_in[3];
    const float* masks = (const float*)d_in[4];
    const int*   tags  = (const int*)d_in[5];
    float* out = (float*)d_out;

    emit_gemm_kernel<<<128, 256>>>(feat, W, bias);
    crf_scan_kernel<<<B_, 64>>>(trans, masks, tags);
    finalize_kernel<<<1, 64>>>(out);
}